// round 10
// baseline (speedup 1.0000x reference)
#include <cuda_runtime.h>
#include <cstdint>

#define B_   2
#define S_   2048
#define D_   1024
#define H_   16
#define DK_  64
#define MTOT (B_ * S_)   // 4096

// ---------------------------------------------------------------------------
// Scratch (device globals — no allocation allowed)
// ---------------------------------------------------------------------------
__device__ float g_Q[MTOT * D_];         // dk col-paired
__device__ float g_K[MTOT * D_];         // dk col-paired
__device__ float g_V[MTOT * D_];         // sequence-row-paired (V' layout)
__device__ float g_att[MTOT * D_];       // D col-paired
__device__ float g_xr[MTOT * D_];        // x, tf32-rounded, D col-paired
__device__ float g_wr[4 * D_ * D_];      // W, tf32-rounded, k-row-paired

// ---------------------------------------------------------------------------
// Helpers (baseline PTX only)
// ---------------------------------------------------------------------------
__device__ __forceinline__ uint32_t smem_u32(const void* p) {
    uint32_t a;
    asm("{ .reg .u64 t; cvta.to.shared.u64 t, %1; cvt.u32.u64 %0, t; }"
        : "=r"(a) : "l"(p));
    return a;
}
__device__ __forceinline__ void cp16(uint32_t s, const void* g) {
    asm volatile("cp.async.cg.shared.global [%0], [%1], 16;"
                 :: "r"(s), "l"(g) : "memory");
}
#define CP_COMMIT() asm volatile("cp.async.commit_group;" ::: "memory")
#define CP_WAIT(n)  asm volatile("cp.async.wait_group %0;" :: "n"(n) : "memory")

__device__ __forceinline__ uint32_t f2tf(float f) {
    uint32_t u;
    asm("cvt.rna.tf32.f32 %0, %1;" : "=r"(u) : "f"(f));
    return u;
}
__device__ __forceinline__ float rtf(float f) {
    return __uint_as_float(f2tf(f));
}
__device__ __forceinline__ void mma_tf32(float* c, const uint32_t* a,
                                         uint32_t b0, uint32_t b1) {
    asm volatile(
        "mma.sync.aligned.m16n8k8.row.col.f32.tf32.tf32.f32 "
        "{%0,%1,%2,%3}, {%4,%5,%6,%7}, {%8,%9}, {%0,%1,%2,%3};"
        : "+f"(c[0]), "+f"(c[1]), "+f"(c[2]), "+f"(c[3])
        : "r"(a[0]), "r"(a[1]), "r"(a[2]), "r"(a[3]), "r"(b0), "r"(b1));
}

// pair permutation within 8-groups: [0,4,1,5,2,6,3,7]
__device__ __forceinline__ int pairc(int c) {
    int r = c & 7;
    return (c & ~7) + ((r < 4) ? (r << 1) : (((r - 4) << 1) | 1));
}

// ---------------------------------------------------------------------------
// Prep: round to tf32-representable fp32 AND emit paired layouts.
// ---------------------------------------------------------------------------
__global__ __launch_bounds__(256) void round_x(const float* __restrict__ in,
                                               float* __restrict__ out)
{
    int i = blockIdx.x * 256 + threadIdx.x;
    float4 v = ((const float4*)in)[i];
    int f0   = i * 4;                       // col ≡ 0 mod 4
    int base = (f0 & ~7) + ((f0 >> 2) & 1); // col-paired positions, stride 2
    out[base + 0] = rtf(v.x);
    out[base + 2] = rtf(v.y);
    out[base + 4] = rtf(v.z);
    out[base + 6] = rtf(v.w);
}

// W[k][n] -> row-paired W' (rows k, k+4 interleaved at element granularity)
__global__ __launch_bounds__(256) void round_w4(const float* __restrict__ w0,
                                                const float* __restrict__ w1,
                                                const float* __restrict__ w2,
                                                const float* __restrict__ w3,
                                                float* __restrict__ dst)
{
    const int by = blockIdx.y;
    const float* src = (by == 0) ? w0 : (by == 1) ? w1 : (by == 2) ? w2 : w3;
    float* out = dst + (size_t)by * D_ * D_;
    int i  = blockIdx.x * 256 + threadIdx.x;
    float4 v = ((const float4*)src)[i];
    int f0 = i * 4;
    int k  = f0 >> 10;           // row (D_=1024)
    int c0 = f0 & 1023;          // col
    size_t rb = (size_t)(k & ~7) * D_ + (size_t)(k & 3) * 2 * D_ + ((k >> 2) & 1);
    out[rb + 2 * (c0 + 0)] = rtf(v.x);
    out[rb + 2 * (c0 + 1)] = rtf(v.y);
    out[rb + 2 * (c0 + 2)] = rtf(v.z);
    out[rb + 2 * (c0 + 3)] = rtf(v.w);
}

// ---------------------------------------------------------------------------
// TF32 GEMM core on paired operands. A col-paired [M,K], W row-paired.
// All fragment loads are LDS.64. Epilogue MODE: 0 plain fp32,
// 1 col-paired+rounded (Q/K), 2 V'-row-paired+rounded (V).
// ---------------------------------------------------------------------------
#define KCH     32
#define APITCH  40                     // ≡ 8 mod 32 -> conflict-free LDS.64
#define BPITCH  264                    // pair-row pitch (256 data + 8 pad)
#define AFLOATS (128 * APITCH)         // 5120
#define BFLOATS (16 * BPITCH)          // 4224
#define ABYTES  (AFLOATS * 4)
#define BBYTES  (BFLOATS * 4)
#define GSMEM   (2 * (ABYTES + BBYTES)) // 74752 B

template <int MODE>
__device__ __forceinline__ void gemm_body(const float* __restrict__ A,
                                          const float* __restrict__ W,
                                          float* __restrict__ C,
                                          int bx, int by, float* sm)
{
    const int tid  = threadIdx.x;
    const int wid  = tid >> 5;
    const int lane = tid & 31;
    const int g    = lane >> 2;
    const int tig  = lane & 3;
    const int m0w  = (wid >> 2) * 64;
    const int n0w  = (wid & 3) * 32;
    const int N    = D_;

    const float* Ab = A + (size_t)by * 128 * D_;
    const uint32_t sbase = smem_u32(sm);

    float acc[4][4][4];
#pragma unroll
    for (int i = 0; i < 4; i++)
#pragma unroll
        for (int j = 0; j < 4; j++)
#pragma unroll
            for (int q = 0; q < 4; q++) acc[i][j][q] = 0.f;

    const int NC = D_ / KCH;   // 32

    auto copy_chunk = [&](int c, int buf) {
        const float* Ac = Ab + c * KCH;
        // W' chunk: 4 row-blocks = contiguous 32*D_, n-slice at 2*bx*128
        const float* Bc = W + (size_t)c * KCH * D_ + 2 * bx * 128;
        uint32_t ab = sbase + (uint32_t)buf * ABYTES;
        uint32_t bb = sbase + 2u * ABYTES + (uint32_t)buf * BBYTES;
#pragma unroll
        for (int p = 0; p < 4; p++) {
            int idx = tid + p * 256;
            int r  = idx >> 3, kq = (idx & 7) << 2;       // A: 128r x 32k
            cp16(ab + (uint32_t)(r * APITCH + kq) * 4, Ac + (size_t)r * D_ + kq);
            int pr = idx >> 6, nq = (idx & 63) << 2;      // B: 16 pair-rows x 256
            cp16(bb + (uint32_t)(pr * BPITCH + nq) * 4,
                 Bc + (size_t)(pr >> 2) * 8 * D_ + (size_t)(pr & 3) * 2 * D_ + nq);
        }
        CP_COMMIT();
    };

    copy_chunk(0, 0);

    for (int c = 0; c < NC; c++) {
        const int buf = c & 1;
        if (c + 1 < NC) { copy_chunk(c + 1, buf ^ 1); CP_WAIT(1); }
        else            { CP_WAIT(0); }
        __syncthreads();

        const float* As = sm + buf * AFLOATS;
        const float* Bs = sm + 2 * AFLOATS + buf * BFLOATS;

#pragma unroll
        for (int kk = 0; kk < KCH; kk += 8) {
            uint32_t a[4][4];
#pragma unroll
            for (int i = 0; i < 4; i++) {
                int r = m0w + 16 * i + g;
                float2 a01 = *(const float2*)&As[r * APITCH + kk + 2 * tig];
                float2 a23 = *(const float2*)&As[(r + 8) * APITCH + kk + 2 * tig];
                a[i][0] = __float_as_uint(a01.x);
                a[i][2] = __float_as_uint(a01.y);
                a[i][1] = __float_as_uint(a23.x);
                a[i][3] = __float_as_uint(a23.y);
            }
#pragma unroll
            for (int j = 0; j < 4; j++) {
                float2 b01 = *(const float2*)
                    &Bs[(kk / 2 + tig) * BPITCH + (n0w + 8 * j + g) * 2];
                uint32_t b0 = __float_as_uint(b01.x);
                uint32_t b1 = __float_as_uint(b01.y);
#pragma unroll
                for (int i = 0; i < 4; i++)
                    mma_tf32(acc[i][j], a[i], b0, b1);
            }
        }
        __syncthreads();
    }

#pragma unroll
    for (int i = 0; i < 4; i++) {
        int r0 = by * 128 + m0w + 16 * i + g;
        int r1 = r0 + 8;
#pragma unroll
        for (int j = 0; j < 4; j++) {
            int cc = bx * 128 + n0w + 8 * j + 2 * tig;
            if (MODE == 0) {
                *(float2*)&C[(size_t)r0 * N + cc] =
                    make_float2(acc[i][j][0], acc[i][j][1]);
                *(float2*)&C[(size_t)r1 * N + cc] =
                    make_float2(acc[i][j][2], acc[i][j][3]);
            } else if (MODE == 1) {          // col-paired + rounded (Q/K)
                C[(size_t)r0 * N + pairc(cc)]     = rtf(acc[i][j][0]);
                C[(size_t)r0 * N + pairc(cc + 1)] = rtf(acc[i][j][1]);
                C[(size_t)r1 * N + pairc(cc)]     = rtf(acc[i][j][2]);
                C[(size_t)r1 * N + pairc(cc + 1)] = rtf(acc[i][j][3]);
            } else {                          // V' row-paired + rounded
                size_t a0 = (size_t)(r0 & ~7) * N + (size_t)(r0 & 3) * 2 * N
                          + ((r0 >> 2) & 1);
                size_t a1 = (size_t)(r1 & ~7) * N + (size_t)(r1 & 3) * 2 * N
                          + ((r1 >> 2) & 1);
                C[a0 + 2 * cc]       = rtf(acc[i][j][0]);
                C[a0 + 2 * (cc + 1)] = rtf(acc[i][j][1]);
                C[a1 + 2 * cc]       = rtf(acc[i][j][2]);
                C[a1 + 2 * (cc + 1)] = rtf(acc[i][j][3]);
            }
        }
    }
}

// Fused Q/K/V projection: gridDim.x = 24; bx/8 selects weight+destination.
__global__ __launch_bounds__(256, 2) void gemm_qkv(const float* __restrict__ x,
                                                   const float* __restrict__ Wr,
                                                   float* __restrict__ Qo,
                                                   float* __restrict__ Ko,
                                                   float* __restrict__ Vo)
{
    extern __shared__ float sm[];
    const int sel = blockIdx.x >> 3;
    const int bx  = blockIdx.x & 7;
    const float* W = Wr + (size_t)sel * D_ * D_;
    if (sel == 0)      gemm_body<1>(x, W, Qo, bx, blockIdx.y, sm);
    else if (sel == 1) gemm_body<1>(x, W, Ko, bx, blockIdx.y, sm);
    else               gemm_body<2>(x, W, Vo, bx, blockIdx.y, sm);
}

// Output projection: plain fp32 output.
__global__ __launch_bounds__(256, 2) void gemm_out(const float* __restrict__ A,
                                                   const float* __restrict__ W,
                                                   float* __restrict__ C)
{
    extern __shared__ float sm[];
    gemm_body<0>(A, W, C, blockIdx.x, blockIdx.y, sm);
}

// ---------------------------------------------------------------------------
// TF32 causal flash attention on paired Q/K/V. All K/V/Q fragment loads are
// LDS.64. P stays plain (pitch 68). Output written D-col-paired for gemm_out.
// smem floats: Q 128x72=9216 (P reuses at 68) | K 2x(64x72) | V' 2x(32x136)
// ---------------------------------------------------------------------------
#define QPITCH  72
#define PPITCH  68
#define VPITCH  136
#define KBUF    (64 * QPITCH)               // 4608
#define VBUF    (32 * VPITCH)               // 4352
#define OFF_K   (128 * QPITCH)              // 9216
#define OFF_V   (OFF_K + 2 * KBUF)          // 18432
#define ASMEM   ((OFF_V + 2 * VBUF) * 4)    // 108544 B

__global__ __launch_bounds__(256, 2) void attn_tc(const float* __restrict__ Q,
                                                  const float* __restrict__ K,
                                                  const float* __restrict__ V,
                                                  float* __restrict__ O)
{
    extern __shared__ float sm[];
    float* QP = sm;                 // Q tile (pitch 72), later P (pitch 68)
    float* Ks = sm + OFF_K;
    float* Vs = sm + OFF_V;

    const int tid  = threadIdx.x;
    const int wid  = tid >> 5;
    const int lane = tid & 31;
    const int g    = lane >> 2;
    const int tig  = lane & 3;

    const int qt = (int)gridDim.x - 1 - (int)blockIdx.x;   // heavy-first
    const int bh = blockIdx.y;
    const int b  = bh >> 4;
    const int h  = bh & 15;

    const size_t base = (size_t)b * S_ * D_ + (size_t)h * DK_;
    const float* Qb = Q + base;
    const float* Kb = K + base;
    const float* Vb = V + (size_t)b * S_ * D_;   // V' indexing needs raw base
    float*       Ob = O + base;
    const int hoff2 = 2 * h * DK_;

    const int q0  = qt * 128;
    const int r0p = wid * 16 + g;
    const uint32_t sb = smem_u32(sm);

    // ---- load Q tile ----
#pragma unroll
    for (int p = 0; p < 8; p++) {
        int idx = tid + p * 256;
        int r = idx >> 4, c = (idx & 15) << 2;
        cp16(sb + (uint32_t)(r * QPITCH + c) * 4,
             Qb + (size_t)(q0 + r) * D_ + c);
    }
    CP_COMMIT();

    auto copy_kv = [&](int t, int buf) {
        const float* Kc = Kb + (size_t)(t * 64) * D_;
        const int kv0 = t * 64;
#pragma unroll
        for (int p = 0; p < 4; p++) {
            int idx = tid + p * 256;
            int r = idx >> 4, c = (idx & 15) << 2;
            cp16(sb + (uint32_t)(OFF_K + buf * KBUF + r * QPITCH + c) * 4,
                 Kc + (size_t)r * D_ + c);
            int pr = idx >> 5, vc = (idx & 31) << 2;
            cp16(sb + (uint32_t)(OFF_V + buf * VBUF + pr * VPITCH + vc) * 4,
                 Vb + (size_t)(kv0 + (pr >> 2) * 8) * D_
                    + (size_t)(pr & 3) * 2 * D_ + hoff2 + vc);
        }
        CP_COMMIT();
    };

    copy_kv(0, 0);

    CP_WAIT(1);
    __syncthreads();

    // ---- preload Q fragments (x1/8 exact; paired cols -> LDS.64) ----
    uint32_t qf[8][4];
#pragma unroll
    for (int kt = 0; kt < 8; kt++) {
        int kk = kt * 8;
        float2 q01 = *(const float2*)&QP[r0p * QPITCH + kk + 2 * tig];
        float2 q23 = *(const float2*)&QP[(r0p + 8) * QPITCH + kk + 2 * tig];
        qf[kt][0] = __float_as_uint(q01.x * 0.125f);
        qf[kt][2] = __float_as_uint(q01.y * 0.125f);
        qf[kt][1] = __float_as_uint(q23.x * 0.125f);
        qf[kt][3] = __float_as_uint(q23.y * 0.125f);
    }
    __syncthreads();    // all warps read Q before P overwrites the region

    float m0 = -1e30f, m1 = -1e30f, l0 = 0.f, l1 = 0.f;
    float o[8][4];
#pragma unroll
    for (int nt = 0; nt < 8; nt++)
#pragma unroll
        for (int c = 0; c < 4; c++) o[nt][c] = 0.f;

    const int qrow0 = q0 + r0p;
    const int qrow1 = qrow0 + 8;
    const int ntiles = 2 * qt + 2;

    for (int t = 0; t < ntiles; t++) {
        const int buf = t & 1;
        CP_WAIT(0);
        __syncthreads();
        if (t + 1 < ntiles) copy_kv(t + 1, buf ^ 1);

        const int kofs = buf * KBUF;
        const int vofs = buf * VBUF;
        const int kv0  = t * 64;

        // ---- scores S = Q @ K^T (K paired -> LDS.64 per fragment) ----
        float sacc[8][4];
#pragma unroll
        for (int nt = 0; nt < 8; nt++)
#pragma unroll
            for (int c = 0; c < 4; c++) sacc[nt][c] = 0.f;

#pragma unroll
        for (int kt = 0; kt < 8; kt++) {
#pragma unroll
            for (int nt = 0; nt < 8; nt++) {
                float2 k01 = *(const float2*)
                    &Ks[kofs + (nt * 8 + g) * QPITCH + kt * 8 + 2 * tig];
                mma_tf32(sacc[nt], qf[kt],
                         __float_as_uint(k01.x), __float_as_uint(k01.y));
            }
        }

        // ---- causal mask ----
        if (kv0 + 63 > q0) {
#pragma unroll
            for (int nt = 0; nt < 8; nt++) {
                int c0 = kv0 + nt * 8 + 2 * tig;
                if (c0     > qrow0) sacc[nt][0] = -1e30f;
                if (c0 + 1 > qrow0) sacc[nt][1] = -1e30f;
                if (c0     > qrow1) sacc[nt][2] = -1e30f;
                if (c0 + 1 > qrow1) sacc[nt][3] = -1e30f;
            }
        }

        // ---- online softmax ----
        float rmax0 = -1e30f, rmax1 = -1e30f;
#pragma unroll
        for (int nt = 0; nt < 8; nt++) {
            rmax0 = fmaxf(rmax0, fmaxf(sacc[nt][0], sacc[nt][1]));
            rmax1 = fmaxf(rmax1, fmaxf(sacc[nt][2], sacc[nt][3]));
        }
        rmax0 = fmaxf(rmax0, __shfl_xor_sync(0xffffffffu, rmax0, 1));
        rmax0 = fmaxf(rmax0, __shfl_xor_sync(0xffffffffu, rmax0, 2));
        rmax1 = fmaxf(rmax1, __shfl_xor_sync(0xffffffffu, rmax1, 1));
        rmax1 = fmaxf(rmax1, __shfl_xor_sync(0xffffffffu, rmax1, 2));

        float mn0 = fmaxf(m0, rmax0), mn1 = fmaxf(m1, rmax1);
        float corr0 = __expf(m0 - mn0), corr1 = __expf(m1 - mn1);
        m0 = mn0; m1 = mn1;

        float ps0 = 0.f, ps1 = 0.f;
#pragma unroll
        for (int nt = 0; nt < 8; nt++) {
            sacc[nt][0] = __expf(sacc[nt][0] - m0);
            sacc[nt][1] = __expf(sacc[nt][1] - m0);
            sacc[nt][2] = __expf(sacc[nt][2] - m1);
            sacc[nt][3] = __expf(sacc[nt][3] - m1);
            ps0 += sacc[nt][0] + sacc[nt][1];
            ps1 += sacc[nt][2] + sacc[nt][3];
            o[nt][0] *= corr0; o[nt][1] *= corr0;
            o[nt][2] *= corr1; o[nt][3] *= corr1;
        }
        l0 = l0 * corr0 + ps0;
        l1 = l1 * corr1 + ps1;

        // ---- store P to smem (plain, pitch 68, tf32-rounded) ----
#pragma unroll
        for (int nt = 0; nt < 8; nt++) {
            *(float2*)&QP[r0p * PPITCH + nt * 8 + 2 * tig] =
                make_float2(rtf(sacc[nt][0]), rtf(sacc[nt][1]));
            *(float2*)&QP[(r0p + 8) * PPITCH + nt * 8 + 2 * tig] =
                make_float2(rtf(sacc[nt][2]), rtf(sacc[nt][3]));
        }
        __syncwarp();

        // ---- O += P @ V (V' paired rows -> LDS.64 per fragment) ----
#pragma unroll
        for (int kt = 0; kt < 8; kt++) {
            uint32_t av[4];
            av[0] = __float_as_uint(QP[r0p * PPITCH + kt * 8 + tig]);
            av[1] = __float_as_uint(QP[(r0p + 8) * PPITCH + kt * 8 + tig]);
            av[2] = __float_as_uint(QP[r0p * PPITCH + kt * 8 + tig + 4]);
            av[3] = __float_as_uint(QP[(r0p + 8) * PPITCH + kt * 8 + tig + 4]);
#pragma unroll
            for (int nt = 0; nt < 8; nt++) {
                float2 v01 = *(const float2*)
                    &Vs[vofs + (kt * 4 + tig) * VPITCH + (nt * 8 + g) * 2];
                mma_tf32(o[nt], av,
                         __float_as_uint(v01.x), __float_as_uint(v01.y));
            }
        }
    }

    // ---- normalize; write D-col-paired + rounded (for gemm_out) ----
    l0 += __shfl_xor_sync(0xffffffffu, l0, 1);
    l0 += __shfl_xor_sync(0xffffffffu, l0, 2);
    l1 += __shfl_xor_sync(0xffffffffu, l1, 1);
    l1 += __shfl_xor_sync(0xffffffffu, l1, 2);
    float inv0 = 1.0f / l0, inv1 = 1.0f / l1;

#pragma unroll
    for (int nt = 0; nt < 8; nt++) {
        int cc = nt * 8 + 2 * tig;
        Ob[(size_t)qrow0 * D_ + pairc(cc)]     = rtf(o[nt][0] * inv0);
        Ob[(size_t)qrow0 * D_ + pairc(cc + 1)] = rtf(o[nt][1] * inv0);
        Ob[(size_t)qrow1 * D_ + pairc(cc)]     = rtf(o[nt][2] * inv1);
        Ob[(size_t)qrow1 * D_ + pairc(cc + 1)] = rtf(o[nt][3] * inv1);
    }
}

// ---------------------------------------------------------------------------
extern "C" void kernel_launch(void* const* d_in, const int* in_sizes, int n_in,
                              void* d_out, int out_size)
{
    (void)in_sizes; (void)n_in; (void)out_size;
    const float* x  = (const float*)d_in[0];
    const float* Wq = (const float*)d_in[1];
    const float* Wk = (const float*)d_in[2];
    const float* Wv = (const float*)d_in[3];
    const float* Wo = (const float*)d_in[4];
    float* out = (float*)d_out;

    float *qp, *kp, *vp, *ap, *xr, *wr;
    cudaGetSymbolAddress((void**)&qp, g_Q);
    cudaGetSymbolAddress((void**)&kp, g_K);
    cudaGetSymbolAddress((void**)&vp, g_V);
    cudaGetSymbolAddress((void**)&ap, g_att);
    cudaGetSymbolAddress((void**)&xr, g_xr);
    cudaGetSymbolAddress((void**)&wr, g_wr);

    cudaFuncSetAttribute(gemm_qkv, cudaFuncAttributeMaxDynamicSharedMemorySize, GSMEM);
    cudaFuncSetAttribute(gemm_out, cudaFuncAttributeMaxDynamicSharedMemorySize, GSMEM);
    cudaFuncSetAttribute(attn_tc,  cudaFuncAttributeMaxDynamicSharedMemorySize, ASMEM);

    round_x<<<(MTOT * D_) / (256 * 4), 256>>>(x, xr);
    round_w4<<<dim3((D_ * D_) / (256 * 4), 4), 256>>>(Wq, Wk, Wv, Wo, wr);

    gemm_qkv<<<dim3(24, MTOT / 128), 256, GSMEM>>>(xr, wr, qp, kp, vp);

    attn_tc<<<dim3(S_ / 128, B_ * H_), 256, ASMEM>>>(qp, kp, vp, ap);

    gemm_out<<<dim3(D_ / 128, MTOT / 128), 256, GSMEM>>>(ap, wr + 3 * (size_t)D_ * D_, out);
}

// round 11
// speedup vs baseline: 1.0387x; 1.0387x over previous
#include <cuda_runtime.h>
#include <cstdint>

#define B_   2
#define S_   2048
#define D_   1024
#define H_   16
#define DK_  64
#define MTOT (B_ * S_)   // 4096

// ---------------------------------------------------------------------------
// Scratch (device globals — no allocation allowed)
// ---------------------------------------------------------------------------
__device__ float g_Q[MTOT * D_];
__device__ float g_K[MTOT * D_];
__device__ float g_V[MTOT * D_];
__device__ float g_att[MTOT * D_];
__device__ float g_xr[MTOT * D_];        // x, tf32-pre-rounded
__device__ float g_wr[4 * D_ * D_];      // Wq,Wk,Wv,Wo, tf32-pre-rounded

// ---------------------------------------------------------------------------
// Helpers (baseline PTX only)
// ---------------------------------------------------------------------------
__device__ __forceinline__ uint32_t smem_u32(const void* p) {
    uint32_t a;
    asm("{ .reg .u64 t; cvta.to.shared.u64 t, %1; cvt.u32.u64 %0, t; }"
        : "=r"(a) : "l"(p));
    return a;
}
__device__ __forceinline__ void cp16(uint32_t s, const void* g) {
    asm volatile("cp.async.cg.shared.global [%0], [%1], 16;"
                 :: "r"(s), "l"(g) : "memory");
}
#define CP_COMMIT() asm volatile("cp.async.commit_group;" ::: "memory")
#define CP_WAIT(n)  asm volatile("cp.async.wait_group %0;" :: "n"(n) : "memory")

__device__ __forceinline__ uint32_t f2tf(float f) {
    uint32_t u;
    asm("cvt.rna.tf32.f32 %0, %1;" : "=r"(u) : "f"(f));
    return u;
}
__device__ __forceinline__ float rtf(float f) {      // round to tf32-representable fp32
    return __uint_as_float(f2tf(f));
}
__device__ __forceinline__ void mma_tf32(float* c, const uint32_t* a,
                                         uint32_t b0, uint32_t b1) {
    asm volatile(
        "mma.sync.aligned.m16n8k8.row.col.f32.tf32.tf32.f32 "
        "{%0,%1,%2,%3}, {%4,%5,%6,%7}, {%8,%9}, {%0,%1,%2,%3};"
        : "+f"(c[0]), "+f"(c[1]), "+f"(c[2]), "+f"(c[3])
        : "r"(a[0]), "r"(a[1]), "r"(a[2]), "r"(a[3]), "r"(b0), "r"(b1));
}

// ---------------------------------------------------------------------------
// Prep: round fp32 -> tf32-representable fp32 (rna), elementwise. Coalesced
// float4 in / float4 out (no layout games — R9 lesson).
// ---------------------------------------------------------------------------
__global__ __launch_bounds__(256) void round_x(const float* __restrict__ in,
                                               float* __restrict__ out)
{
    int i = blockIdx.x * 256 + threadIdx.x;
    float4 v = ((const float4*)in)[i];
    ((float4*)out)[i] = make_float4(rtf(v.x), rtf(v.y), rtf(v.z), rtf(v.w));
}

__global__ __launch_bounds__(256) void round_w4(const float* __restrict__ w0,
                                                const float* __restrict__ w1,
                                                const float* __restrict__ w2,
                                                const float* __restrict__ w3,
                                                float* __restrict__ dst)
{
    const int by = blockIdx.y;
    const float* src = (by == 0) ? w0 : (by == 1) ? w1 : (by == 2) ? w2 : w3;
    int i = blockIdx.x * 256 + threadIdx.x;
    float4 v = ((const float4*)src)[i];
    ((float4*)(dst + (size_t)by * D_ * D_))[i] =
        make_float4(rtf(v.x), rtf(v.y), rtf(v.z), rtf(v.w));
}

// ---------------------------------------------------------------------------
// TF32 GEMM core. Operands tf32-pre-rounded -> plain LDS fragment loads.
// 3-stage circular cp.async pipeline: copy chunk c+2 while computing c;
// ONE __syncthreads per chunk (the top-of-iter barrier also protects the
// stage about to be overwritten, since target (c+2)%3 == (c-1)%3's reader
// set has all passed it). Compute order identical to R8 -> bit-identical.
// ---------------------------------------------------------------------------
#define KCH     32
#define APITCH  36
#define BPITCH  136
#define AFLOATS (128 * APITCH)          // 4608
#define BFLOATS (KCH * BPITCH)          // 4352
#define STAGEF  (AFLOATS + BFLOATS)     // 8960 floats
#define STAGEB  (STAGEF * 4)            // 35840 B
#define GSMEM   (3 * STAGEB)            // 107520 B

template <int ROUND>
__device__ __forceinline__ void gemm_body(const float* __restrict__ A,
                                          const float* __restrict__ W,
                                          float* __restrict__ C,
                                          int bx, int by, int N, int K,
                                          float* sm)
{
    const int tid  = threadIdx.x;
    const int wid  = tid >> 5;
    const int lane = tid & 31;
    const int g    = lane >> 2;
    const int tig  = lane & 3;
    const int m0w  = (wid >> 2) * 64;
    const int n0w  = (wid & 3) * 32;

    const float* Ab = A + (size_t)by * 128 * K;
    const float* Wb = W + bx * 128;
    const uint32_t sbase = smem_u32(sm);

    float acc[4][4][4];
#pragma unroll
    for (int i = 0; i < 4; i++)
#pragma unroll
        for (int j = 0; j < 4; j++)
#pragma unroll
            for (int q = 0; q < 4; q++) acc[i][j][q] = 0.f;

    const int NC = K / KCH;   // 32

    auto copy_chunk = [&](int c, int buf) {
        const float* Ac = Ab + c * KCH;
        const float* Bc = Wb + (size_t)c * KCH * N;
        uint32_t ab = sbase + (uint32_t)buf * STAGEB;
        uint32_t bb = ab + (uint32_t)(AFLOATS * 4);
#pragma unroll
        for (int p = 0; p < 4; p++) {
            int idx = tid + p * 256;
            int r  = idx >> 3, kq = (idx & 7) << 2;
            cp16(ab + (uint32_t)(r * APITCH + kq) * 4, Ac + (size_t)r * K + kq);
            int kb = idx >> 5, nq = (idx & 31) << 2;
            cp16(bb + (uint32_t)(kb * BPITCH + nq) * 4, Bc + (size_t)kb * N + nq);
        }
        CP_COMMIT();
    };

    copy_chunk(0, 0);
    copy_chunk(1, 1);

    int bufc = 0;          // compute stage = c % 3
    int bufn = 2;          // copy target  = (c+2) % 3

    for (int c = 0; c < NC; c++) {
        if (c + 1 < NC) { CP_WAIT(1); }   // chunk c complete (c+1 may fly)
        else            { CP_WAIT(0); }
        __syncthreads();                  // all warps done with stage bufn's old data
        if (c + 2 < NC) {
            copy_chunk(c + 2, bufn);
            bufn = (bufn == 2) ? 0 : bufn + 1;
        }

        const float* As = sm + bufc * STAGEF;
        const float* Bs = As + AFLOATS;
        bufc = (bufc == 2) ? 0 : bufc + 1;

#pragma unroll
        for (int kk = 0; kk < KCH; kk += 8) {
            uint32_t a[4][4];
#pragma unroll
            for (int i = 0; i < 4; i++) {
                int r = m0w + 16 * i + g;
                a[i][0] = __float_as_uint(As[r * APITCH + kk + tig]);
                a[i][1] = __float_as_uint(As[(r + 8) * APITCH + kk + tig]);
                a[i][2] = __float_as_uint(As[r * APITCH + kk + tig + 4]);
                a[i][3] = __float_as_uint(As[(r + 8) * APITCH + kk + tig + 4]);
            }
#pragma unroll
            for (int j = 0; j < 4; j++) {
                uint32_t b0 = __float_as_uint(Bs[(kk + tig) * BPITCH + n0w + 8 * j + g]);
                uint32_t b1 = __float_as_uint(Bs[(kk + tig + 4) * BPITCH + n0w + 8 * j + g]);
#pragma unroll
                for (int i = 0; i < 4; i++)
                    mma_tf32(acc[i][j], a[i], b0, b1);
            }
        }
        // no trailing barrier: next iteration's top barrier protects reuse
    }

#pragma unroll
    for (int i = 0; i < 4; i++) {
        int r0 = by * 128 + m0w + 16 * i + g;
#pragma unroll
        for (int j = 0; j < 4; j++) {
            int cc = bx * 128 + n0w + 8 * j + 2 * tig;
            if (ROUND) {
                *(float2*)&C[(size_t)r0 * N + cc] =
                    make_float2(rtf(acc[i][j][0]), rtf(acc[i][j][1]));
                *(float2*)&C[(size_t)(r0 + 8) * N + cc] =
                    make_float2(rtf(acc[i][j][2]), rtf(acc[i][j][3]));
            } else {
                *(float2*)&C[(size_t)r0 * N + cc] =
                    make_float2(acc[i][j][0], acc[i][j][1]);
                *(float2*)&C[(size_t)(r0 + 8) * N + cc] =
                    make_float2(acc[i][j][2], acc[i][j][3]);
            }
        }
    }
}

// Fused Q/K/V projection: gridDim.x = 24; bx/8 selects weight+destination.
__global__ __launch_bounds__(256, 2) void gemm_qkv(const float* __restrict__ x,
                                                   const float* __restrict__ Wr,
                                                   float* __restrict__ Qo,
                                                   float* __restrict__ Ko,
                                                   float* __restrict__ Vo)
{
    extern __shared__ float sm[];
    const int sel = blockIdx.x >> 3;
    const int bx  = blockIdx.x & 7;
    const float* W = Wr + (size_t)sel * D_ * D_;
    float*       C = (sel == 0) ? Qo : (sel == 1) ? Ko : Vo;
    gemm_body<1>(x, W, C, bx, blockIdx.y, D_, D_, sm);
}

// Output projection: full fp32 output (no rounding).
__global__ __launch_bounds__(256, 2) void gemm_out(const float* __restrict__ A,
                                                   const float* __restrict__ W,
                                                   float* __restrict__ C)
{
    extern __shared__ float sm[];
    gemm_body<0>(A, W, C, blockIdx.x, blockIdx.y, D_, D_, sm);
}

// ---------------------------------------------------------------------------
// TF32 tensor-core causal flash attention (identical to R8 — known 196 us,
// bit-exact numerics). Q/K/V tf32-pre-rounded -> plain LDS fragment loads.
// ---------------------------------------------------------------------------
#define QPITCH  68
#define VPITCH  72
#define OFF_K   8704
#define OFF_V   (8704 + 2 * 4352)
#define KBUF    4352                  // 64*68 floats
#define VBUF    4608                  // 64*72 floats
#define ASMEM   ((OFF_V + 2 * VBUF) * 4)   // 106496 B

__global__ __launch_bounds__(256, 2) void attn_tc(const float* __restrict__ Q,
                                                  const float* __restrict__ K,
                                                  const float* __restrict__ V,
                                                  float* __restrict__ O)
{
    extern __shared__ float sm[];
    float* QP = sm;                 // Q tile, later P tile
    float* Ks = sm + OFF_K;
    float* Vs = sm + OFF_V;

    const int tid  = threadIdx.x;
    const int wid  = tid >> 5;
    const int lane = tid & 31;
    const int g    = lane >> 2;
    const int tig  = lane & 3;

    const int qt = (int)gridDim.x - 1 - (int)blockIdx.x;   // heavy-first
    const int bh = blockIdx.y;
    const int b  = bh >> 4;
    const int h  = bh & 15;

    const size_t base = (size_t)b * S_ * D_ + (size_t)h * DK_;
    const float* Qb = Q + base;
    const float* Kb = K + base;
    const float* Vb = V + base;
    float*       Ob = O + base;

    const int q0  = qt * 128;
    const int r0p = wid * 16 + g;
    const uint32_t sb = smem_u32(sm);

    // ---- load Q tile (group 1) ----
#pragma unroll
    for (int p = 0; p < 8; p++) {
        int idx = tid + p * 256;
        int r = idx >> 4, c = (idx & 15) << 2;
        cp16(sb + (uint32_t)(r * QPITCH + c) * 4,
             Qb + (size_t)(q0 + r) * D_ + c);
    }
    CP_COMMIT();

    auto copy_kv = [&](int t, int buf) {
        const float* Kc = Kb + (size_t)(t * 64) * D_;
        const float* Vc = Vb + (size_t)(t * 64) * D_;
#pragma unroll
        for (int p = 0; p < 4; p++) {
            int idx = tid + p * 256;
            int r = idx >> 4, c = (idx & 15) << 2;
            cp16(sb + (uint32_t)(OFF_K + buf * KBUF + r * QPITCH + c) * 4,
                 Kc + (size_t)r * D_ + c);
            cp16(sb + (uint32_t)(OFF_V + buf * VBUF + r * VPITCH + c) * 4,
                 Vc + (size_t)r * D_ + c);
        }
        CP_COMMIT();
    };

    copy_kv(0, 0);      // group 2

    CP_WAIT(1);         // Q ready (kv0 may be in flight)
    __syncthreads();

    // ---- preload Q fragments (x 1/8 = exponent shift, stays tf32-exact) ----
    uint32_t qf[8][4];
#pragma unroll
    for (int kt = 0; kt < 8; kt++) {
        int kk = kt * 8;
        qf[kt][0] = __float_as_uint(QP[r0p * QPITCH + kk + tig] * 0.125f);
        qf[kt][1] = __float_as_uint(QP[(r0p + 8) * QPITCH + kk + tig] * 0.125f);
        qf[kt][2] = __float_as_uint(QP[r0p * QPITCH + kk + tig + 4] * 0.125f);
        qf[kt][3] = __float_as_uint(QP[(r0p + 8) * QPITCH + kk + tig + 4] * 0.125f);
    }
    __syncthreads();    // all warps read Q before P overwrites the region

    float m0 = -1e30f, m1 = -1e30f, l0 = 0.f, l1 = 0.f;
    float o[8][4];
#pragma unroll
    for (int nt = 0; nt < 8; nt++)
#pragma unroll
        for (int c = 0; c < 4; c++) o[nt][c] = 0.f;

    const int qrow0 = q0 + r0p;
    const int qrow1 = qrow0 + 8;
    const int ntiles = 2 * qt + 2;

    for (int t = 0; t < ntiles; t++) {
        const int buf = t & 1;
        CP_WAIT(0);
        __syncthreads();            // tile t ready; all warps done with t-1
        if (t + 1 < ntiles) copy_kv(t + 1, buf ^ 1);

        const int kofs = buf * KBUF;
        const int vofs = buf * VBUF;
        const int kv0  = t * 64;

        // ---- scores S = Q @ K^T ----
        float sacc[8][4];
#pragma unroll
        for (int nt = 0; nt < 8; nt++)
#pragma unroll
            for (int c = 0; c < 4; c++) sacc[nt][c] = 0.f;

#pragma unroll
        for (int kt = 0; kt < 8; kt++) {
#pragma unroll
            for (int nt = 0; nt < 8; nt++) {
                const float* kb = &Ks[kofs + (nt * 8 + g) * QPITCH + kt * 8 + tig];
                uint32_t b0 = __float_as_uint(kb[0]);
                uint32_t b1 = __float_as_uint(kb[4]);
                mma_tf32(sacc[nt], qf[kt], b0, b1);
            }
        }

        // ---- causal mask (only tiles intersecting the diagonal) ----
        if (kv0 + 63 > q0) {
#pragma unroll
            for (int nt = 0; nt < 8; nt++) {
                int c0 = kv0 + nt * 8 + 2 * tig;
                if (c0     > qrow0) sacc[nt][0] = -1e30f;
                if (c0 + 1 > qrow0) sacc[nt][1] = -1e30f;
                if (c0     > qrow1) sacc[nt][2] = -1e30f;
                if (c0 + 1 > qrow1) sacc[nt][3] = -1e30f;
            }
        }

        // ---- online softmax (rows live on 4-lane groups) ----
        float rmax0 = -1e30f, rmax1 = -1e30f;
#pragma unroll
        for (int nt = 0; nt < 8; nt++) {
            rmax0 = fmaxf(rmax0, fmaxf(sacc[nt][0], sacc[nt][1]));
            rmax1 = fmaxf(rmax1, fmaxf(sacc[nt][2], sacc[nt][3]));
        }
        rmax0 = fmaxf(rmax0, __shfl_xor_sync(0xffffffffu, rmax0, 1));
        rmax0 = fmaxf(rmax0, __shfl_xor_sync(0xffffffffu, rmax0, 2));
        rmax1 = fmaxf(rmax1, __shfl_xor_sync(0xffffffffu, rmax1, 1));
        rmax1 = fmaxf(rmax1, __shfl_xor_sync(0xffffffffu, rmax1, 2));

        float mn0 = fmaxf(m0, rmax0), mn1 = fmaxf(m1, rmax1);
        float corr0 = __expf(m0 - mn0), corr1 = __expf(m1 - mn1);
        m0 = mn0; m1 = mn1;

        float ps0 = 0.f, ps1 = 0.f;
#pragma unroll
        for (int nt = 0; nt < 8; nt++) {
            sacc[nt][0] = __expf(sacc[nt][0] - m0);
            sacc[nt][1] = __expf(sacc[nt][1] - m0);
            sacc[nt][2] = __expf(sacc[nt][2] - m1);
            sacc[nt][3] = __expf(sacc[nt][3] - m1);
            ps0 += sacc[nt][0] + sacc[nt][1];
            ps1 += sacc[nt][2] + sacc[nt][3];
            o[nt][0] *= corr0; o[nt][1] *= corr0;
            o[nt][2] *= corr1; o[nt][3] *= corr1;
        }
        l0 = l0 * corr0 + ps0;
        l1 = l1 * corr1 + ps1;

        // ---- store P to smem, tf32-rounded (warp-private rows) ----
#pragma unroll
        for (int nt = 0; nt < 8; nt++) {
            *(float2*)&QP[r0p * QPITCH + nt * 8 + 2 * tig] =
                make_float2(rtf(sacc[nt][0]), rtf(sacc[nt][1]));
            *(float2*)&QP[(r0p + 8) * QPITCH + nt * 8 + 2 * tig] =
                make_float2(rtf(sacc[nt][2]), rtf(sacc[nt][3]));
        }
        __syncwarp();

        // ---- O += P @ V ----
#pragma unroll
        for (int kt = 0; kt < 8; kt++) {
            uint32_t av[4];
            av[0] = __float_as_uint(QP[r0p * QPITCH + kt * 8 + tig]);
            av[1] = __float_as_uint(QP[(r0p + 8) * QPITCH + kt * 8 + tig]);
            av[2] = __float_as_uint(QP[r0p * QPITCH + kt * 8 + tig + 4]);
            av[3] = __float_as_uint(QP[(r0p + 8) * QPITCH + kt * 8 + tig + 4]);
#pragma unroll
            for (int nt = 0; nt < 8; nt++) {
                const float* vb = &Vs[vofs + (kt * 8 + tig) * VPITCH + nt * 8 + g];
                uint32_t b0 = __float_as_uint(vb[0]);
                uint32_t b1 = __float_as_uint(vb[4 * VPITCH]);
                mma_tf32(o[nt], av, b0, b1);
            }
        }
        // next iteration's leading __syncthreads orders P reads vs next store
    }

    // ---- normalize and write (tf32-rounded for gemm_out) ----
    l0 += __shfl_xor_sync(0xffffffffu, l0, 1);
    l0 += __shfl_xor_sync(0xffffffffu, l0, 2);
    l1 += __shfl_xor_sync(0xffffffffu, l1, 1);
    l1 += __shfl_xor_sync(0xffffffffu, l1, 2);
    float inv0 = 1.0f / l0, inv1 = 1.0f / l1;

#pragma unroll
    for (int nt = 0; nt < 8; nt++) {
        int cc = nt * 8 + 2 * tig;
        *(float2*)&Ob[(size_t)qrow0 * D_ + cc] =
            make_float2(rtf(o[nt][0] * inv0), rtf(o[nt][1] * inv0));
        *(float2*)&Ob[(size_t)qrow1 * D_ + cc] =
            make_float2(rtf(o[nt][2] * inv1), rtf(o[nt][3] * inv1));
    }
}

// ---------------------------------------------------------------------------
extern "C" void kernel_launch(void* const* d_in, const int* in_sizes, int n_in,
                              void* d_out, int out_size)
{
    (void)in_sizes; (void)n_in; (void)out_size;
    const float* x  = (const float*)d_in[0];
    const float* Wq = (const float*)d_in[1];
    const float* Wk = (const float*)d_in[2];
    const float* Wv = (const float*)d_in[3];
    const float* Wo = (const float*)d_in[4];
    float* out = (float*)d_out;

    float *qp, *kp, *vp, *ap, *xr, *wr;
    cudaGetSymbolAddress((void**)&qp, g_Q);
    cudaGetSymbolAddress((void**)&kp, g_K);
    cudaGetSymbolAddress((void**)&vp, g_V);
    cudaGetSymbolAddress((void**)&ap, g_att);
    cudaGetSymbolAddress((void**)&xr, g_xr);
    cudaGetSymbolAddress((void**)&wr, g_wr);

    cudaFuncSetAttribute(gemm_qkv, cudaFuncAttributeMaxDynamicSharedMemorySize, GSMEM);
    cudaFuncSetAttribute(gemm_out, cudaFuncAttributeMaxDynamicSharedMemorySize, GSMEM);
    cudaFuncSetAttribute(attn_tc,  cudaFuncAttributeMaxDynamicSharedMemorySize, ASMEM);

    // Pre-round all GEMM operands to tf32-representable fp32
    round_x<<<(MTOT * D_) / (256 * 4), 256>>>(x, xr);
    round_w4<<<dim3((D_ * D_) / (256 * 4), 4), 256>>>(Wq, Wk, Wv, Wo, wr);

    gemm_qkv<<<dim3(24, MTOT / 128), 256, GSMEM>>>(xr, wr, qp, kp, vp);

    attn_tc<<<dim3(S_ / 128, B_ * H_), 256, ASMEM>>>(qp, kp, vp, ap);

    gemm_out<<<dim3(D_ / 128, MTOT / 128), 256, GSMEM>>>(ap, wr + 3 * (size_t)D_ * D_, out);
}